// round 14
// baseline (speedup 1.0000x reference)
#include <cuda_runtime.h>
#include <cstdint>
#include <math.h>

#define BB 8192
#define TT 128
#define DD 7
#define CC 10
#define LL 128
#define NCOL (TT*DD)   // 896
#define NGR 16         // tree groups
#define TPG (TT/NGR)   // 8 trees per group

// Scratch (device globals: allocation-free rule)
__device__ __align__(16) float g_s[(size_t)NCOL*BB];      // s[col][b]
__device__ __align__(16) float g_attn[(size_t)TT*BB];     // attn[t][b]
__device__ __align__(16) float g_lpf2[TT*16*32*2];        // c0 B frags [t][ks][lane]{b0,b1} (tf32-RNA)
__device__ __align__(16) float g_lp89q[TT*16*4*4];        // [t][ks][tg]{lp8(tg),lp9(tg),lp8(tg+4),lp9(tg+4)} fp32
__device__ __align__(16) float g_partial[(size_t)NGR*BB*CC];

typedef unsigned long long ull;

// ---- packed fp32x2 helpers ------------------------------------------------
__device__ __forceinline__ ull pk2(float lo, float hi) {
    ull r;
    asm("mov.b64 %0, {%1, %2};" : "=l"(r) : "f"(lo), "f"(hi));
    return r;
}
__device__ __forceinline__ void upk2(ull v, float& lo, float& hi) {
    asm("mov.b64 {%0, %1}, %2;" : "=f"(lo), "=f"(hi) : "l"(v));
}
__device__ __forceinline__ ull fma2(ull a, ull b, ull c) {
    ull d;
    asm("fma.rn.f32x2 %0, %1, %2, %3;" : "=l"(d) : "l"(a), "l"(b), "l"(c));
    return d;
}
__device__ __forceinline__ ull mul2(ull a, ull b) {
    ull d;
    asm("mul.rn.f32x2 %0, %1, %2;" : "=l"(d) : "l"(a), "l"(b));
    return d;
}

// ---- tf32 / bf16 helpers ---------------------------------------------------
__device__ __forceinline__ float rna_tf32(float x) {
    float o;
    asm("cvt.rna.tf32.f32 %0, %1;" : "=f"(o) : "f"(x));
    return o;
}
__device__ __forceinline__ void mma_tf32(float* c, uint32_t a0, uint32_t a1,
                                         uint32_t a2, uint32_t a3,
                                         uint32_t b0, uint32_t b1) {
    asm volatile(
        "mma.sync.aligned.m16n8k8.row.col.f32.tf32.tf32.f32 "
        "{%0,%1,%2,%3}, {%4,%5,%6,%7}, {%8,%9}, {%0,%1,%2,%3};"
        : "+f"(c[0]), "+f"(c[1]), "+f"(c[2]), "+f"(c[3])
        : "r"(a0), "r"(a1), "r"(a2), "r"(a3), "r"(b0), "r"(b1));
}
__device__ __forceinline__ void mma_bf16(float* c, uint32_t a0, uint32_t a1,
                                         uint32_t a2, uint32_t a3,
                                         uint32_t b0, uint32_t b1) {
    asm volatile(
        "mma.sync.aligned.m16n8k16.row.col.f32.bf16.bf16.f32 "
        "{%0,%1,%2,%3}, {%4,%5,%6,%7}, {%8,%9}, {%0,%1,%2,%3};"
        : "+f"(c[0]), "+f"(c[1]), "+f"(c[2]), "+f"(c[3])
        : "r"(a0), "r"(a1), "r"(a2), "r"(a3), "r"(b0), "r"(b1));
}
// pack: lower 16 bits = bf16(even), upper = bf16(odd)
__device__ __forceinline__ uint32_t bf16x2_of(float even, float odd) {
    uint32_t d;
    asm("cvt.rn.bf16x2.f32 %0, %1, %2;" : "=r"(d) : "f"(odd), "f"(even));
    return d;
}

// ---------------------------------------------------------------------------
// Kernel 1: leaf softmax -> c0 B fragments (tf32-RNA) + fp32 lp89 quad table
// ---------------------------------------------------------------------------
__global__ void k_leafprep(const float* __restrict__ leaf) {
    int row = blockIdx.x * 256 + threadIdx.x;
    if (row >= TT * LL) return;
    int t = row >> 7, l = row & 127;
    const float* in = leaf + (size_t)row * CC;
    float m = in[0];
#pragma unroll
    for (int c = 1; c < CC; c++) m = fmaxf(m, in[c]);
    float e[CC]; float sum = 0.f;
#pragma unroll
    for (int c = 0; c < CC; c++) { e[c] = __expf(in[c] - m); sum += e[c]; }
    float inv = __fdividef(1.f, sum);
    float lp[CC];
#pragma unroll
    for (int c = 0; c < CC; c++) lp[c] = e[c] * inv;

    int ks = l >> 3, kk = l & 7, tg = kk & 3, slot = kk >> 2;
    float* base = g_lpf2 + (size_t)((t * 16 + ks) * 32) * 2;
#pragma unroll
    for (int gid = 0; gid < 8; gid++)
        base[(gid * 4 + tg) * 2 + slot] = rna_tf32(lp[gid]);

    // lp89 quad table: slot 0 -> (.x,.y), slot 1 -> (.z,.w); full fp32
    float* q = g_lp89q + (size_t)(((t * 16 + ks) * 4 + tg) * 4);
    q[slot * 2 + 0] = lp[8];
    q[slot * 2 + 1] = lp[9];
}

// ---------------------------------------------------------------------------
// Kernel 2: z = x @ FM^T - th, s = 0.5*(z/(1+|z|)+1)  -> g_s[col][b]
// bf16 m16n8k16 with hi/lo K-packing (unchanged from round 9).
// ---------------------------------------------------------------------------
__global__ __launch_bounds__(256) void k_zs_mma(const float* __restrict__ x,
                                                const float* __restrict__ fm,
                                                const float* __restrict__ th) {
    int tid = threadIdx.x;
    int warp = tid >> 5, lane = tid & 31;
    int gid = lane >> 2, tg = lane & 3;
    int rbase = blockIdx.x * 256 + warp * 32 + gid;   // rows rbase, +8, +16, +24
    int bn = blockIdx.y * 56;

    float c[2][7][4];
#pragma unroll
    for (int mf = 0; mf < 2; mf++)
#pragma unroll
        for (int nt = 0; nt < 7; nt++)
#pragma unroll
            for (int q = 0; q < 4; q++) c[mf][nt][q] = 0.f;

    const float* xr0 = x + (size_t)rbase * 128;
    const float* xr1 = x + (size_t)(rbase + 8) * 128;
    const float* xr2 = x + (size_t)(rbase + 16) * 128;
    const float* xr3 = x + (size_t)(rbase + 24) * 128;

#pragma unroll
    for (int ks = 0; ks < 16; ks++) {
        int kb = ks * 8 + 2 * tg;           // this thread's 2 adjacent features
        const float* xrs[4] = {xr0, xr1, xr2, xr3};
        uint32_t ah[4], al[4];
#pragma unroll
        for (int r = 0; r < 4; r++) {
            float2 xv = __ldg((const float2*)(xrs[r] + kb));
            uint32_t h = bf16x2_of(xv.x, xv.y);
            float fe = __uint_as_float(h << 16);
            float fo = __uint_as_float(h & 0xffff0000u);
            ah[r] = h;
            al[r] = bf16x2_of(xv.x - fe, xv.y - fo);   // exact residual, bf16-rounded
        }
#pragma unroll
        for (int nt = 0; nt < 7; nt++) {
            int col = bn + nt * 8 + gid;
            float2 fv = __ldg((const float2*)(fm + (size_t)col * 128 + kb));
            uint32_t bb = bf16x2_of(fv.x, fv.y);       // 0/1: exact
            mma_bf16(c[0][nt], ah[0], ah[1], al[0], al[1], bb, bb);
            mma_bf16(c[1][nt], ah[2], ah[3], al[2], al[3], bb, bb);
        }
    }

#pragma unroll
    for (int mf = 0; mf < 2; mf++) {
        int b0r = rbase + mf * 16;
#pragma unroll
        for (int nt = 0; nt < 7; nt++) {
            int col = bn + nt * 8 + tg * 2;
            float t0v = __ldg(th + col), t1v = __ldg(th + col + 1);
            float z0 = c[mf][nt][0] - t0v;
            float z1 = c[mf][nt][1] - t1v;
            float z2 = c[mf][nt][2] - t0v;
            float z3 = c[mf][nt][3] - t1v;
            g_s[(size_t)col * BB + b0r]           = 0.5f * (__fdividef(z0, 1.0f + fabsf(z0)) + 1.0f);
            g_s[(size_t)(col + 1) * BB + b0r]     = 0.5f * (__fdividef(z1, 1.0f + fabsf(z1)) + 1.0f);
            g_s[(size_t)col * BB + b0r + 8]       = 0.5f * (__fdividef(z2, 1.0f + fabsf(z2)) + 1.0f);
            g_s[(size_t)(col + 1) * BB + b0r + 8] = 0.5f * (__fdividef(z3, 1.0f + fabsf(z3)) + 1.0f);
        }
    }
}

// ---------------------------------------------------------------------------
// Kernel 3: attn = softmax(relu(x@W1+b1)@W2+b2)  -> g_attn[t][b]
// ---------------------------------------------------------------------------
__global__ __launch_bounds__(256) void k_attn(const float* __restrict__ x,
                                              const float* __restrict__ W1,
                                              const float* __restrict__ b1,
                                              const float* __restrict__ W2,
                                              const float* __restrict__ b2) {
    __shared__ __align__(16) float xst[128 * 32];
    __shared__ __align__(16) float hst[64 * 32];
    __shared__ __align__(16) float stage[128 * 33];
    int tid = threadIdx.x;
    int b0 = blockIdx.x * 32;
#pragma unroll
    for (int j = 0; j < 4; j++) {
        int idx = tid + 256 * j;
        int bl = idx & 31;
        int kq = (idx >> 5) * 4;
        float4 v = *(const float4*)(x + (size_t)(b0 + bl) * 128 + kq);
        xst[(kq + 0) * 32 + bl] = v.x; xst[(kq + 1) * 32 + bl] = v.y;
        xst[(kq + 2) * 32 + bl] = v.z; xst[(kq + 3) * 32 + bl] = v.w;
    }
    int bl = tid & 31;
    int grp = tid >> 5;
    ull hacc2[4] = {0ull, 0ull, 0ull, 0ull};
    for (int kc = 0; kc < 128; kc += 64) {
        __syncthreads();
#pragma unroll
        for (int j = 0; j < 4; j++) {
            int idx = tid + 256 * j;
            ((float4*)stage)[idx] = *((const float4*)(W1 + (size_t)kc * 64) + idx);
        }
        __syncthreads();
#pragma unroll 8
        for (int k = 0; k < 64; k++) {
            float xv = xst[(kc + k) * 32 + bl];
            ull xp = pk2(xv, xv);
            ulonglong2 w0 = *(const ulonglong2*)&stage[k * 64 + grp * 8];
            ulonglong2 w1 = *(const ulonglong2*)&stage[k * 64 + grp * 8 + 4];
            hacc2[0] = fma2(xp, w0.x, hacc2[0]);
            hacc2[1] = fma2(xp, w0.y, hacc2[1]);
            hacc2[2] = fma2(xp, w1.x, hacc2[2]);
            hacc2[3] = fma2(xp, w1.y, hacc2[3]);
        }
    }
#pragma unroll
    for (int jj = 0; jj < 4; jj++) {
        float h0, h1;
        upk2(hacc2[jj], h0, h1);
        h0 += __ldg(b1 + grp * 8 + 2 * jj);
        h1 += __ldg(b1 + grp * 8 + 2 * jj + 1);
        hst[(grp * 8 + 2 * jj) * 32 + bl] = fmaxf(h0, 0.f);
        hst[(grp * 8 + 2 * jj + 1) * 32 + bl] = fmaxf(h1, 0.f);
    }
    ull lacc2[8];
#pragma unroll
    for (int j = 0; j < 8; j++) lacc2[j] = 0ull;
    for (int kc = 0; kc < 64; kc += 32) {
        __syncthreads();
#pragma unroll
        for (int j = 0; j < 4; j++) {
            int idx = tid + 256 * j;
            ((float4*)stage)[idx] = *((const float4*)(W2 + (size_t)kc * 128) + idx);
        }
        __syncthreads();
#pragma unroll 4
        for (int k = 0; k < 32; k++) {
            float hv = hst[(kc + k) * 32 + bl];
            ull hp = pk2(hv, hv);
            const ulonglong2* wr = (const ulonglong2*)&stage[k * 128 + grp * 16];
            ulonglong2 q0 = wr[0], q1 = wr[1], q2 = wr[2], q3 = wr[3];
            lacc2[0] = fma2(hp, q0.x, lacc2[0]); lacc2[1] = fma2(hp, q0.y, lacc2[1]);
            lacc2[2] = fma2(hp, q1.x, lacc2[2]); lacc2[3] = fma2(hp, q1.y, lacc2[3]);
            lacc2[4] = fma2(hp, q2.x, lacc2[4]); lacc2[5] = fma2(hp, q2.y, lacc2[5]);
            lacc2[6] = fma2(hp, q3.x, lacc2[6]); lacc2[7] = fma2(hp, q3.y, lacc2[7]);
        }
    }
    __syncthreads();
#pragma unroll
    for (int jj = 0; jj < 8; jj++) {
        float l0, l1;
        upk2(lacc2[jj], l0, l1);
        stage[(grp * 16 + 2 * jj) * 33 + bl] = l0 + __ldg(b2 + grp * 16 + 2 * jj);
        stage[(grp * 16 + 2 * jj + 1) * 33 + bl] = l1 + __ldg(b2 + grp * 16 + 2 * jj + 1);
    }
    __syncthreads();
    int lane = bl;
    for (int r4 = 0; r4 < 4; r4++) {
        int r = grp * 4 + r4;
        float v0 = stage[(lane +  0) * 33 + r];
        float v1 = stage[(lane + 32) * 33 + r];
        float v2 = stage[(lane + 64) * 33 + r];
        float v3 = stage[(lane + 96) * 33 + r];
        float m = fmaxf(fmaxf(v0, v1), fmaxf(v2, v3));
#pragma unroll
        for (int o = 16; o > 0; o >>= 1) m = fmaxf(m, __shfl_xor_sync(0xffffffffu, m, o));
        float e0 = __expf(v0 - m), e1 = __expf(v1 - m), e2 = __expf(v2 - m), e3 = __expf(v3 - m);
        float s = e0 + e1 + e2 + e3;
#pragma unroll
        for (int o = 16; o > 0; o >>= 1) s += __shfl_xor_sync(0xffffffffu, s, o);
        float inv = __fdividef(1.f, s);
        int gb = b0 + r;
        g_attn[(size_t)(lane +  0) * BB + gb] = e0 * inv;
        g_attn[(size_t)(lane + 32) * BB + gb] = e1 * inv;
        g_attn[(size_t)(lane + 64) * BB + gb] = e2 * inv;
        g_attn[(size_t)(lane + 96) * BB + gb] = e3 * inv;
    }
}

// ---------------------------------------------------------------------------
// Kernel 4: tree eval. Classes 0..7: 16 tf32 HMMA/tree (4 chains).
// Classes 8,9: fma2 on the same a01/a23 operands + quad-uniform LDG.128
// lp89 table (no smem, fp32 exact). HMMA count halved vs round 7.
// ---------------------------------------------------------------------------
__global__ __launch_bounds__(256, 3) void k_trees_mma() {
    int tid = threadIdx.x;
    int warp = tid >> 5, lane = tid & 31;
    int gid = lane >> 2, tg = lane & 3;
    int r0 = blockIdx.x * 128 + warp * 16 + gid;
    int r1 = r0 + 8;
    int t0 = blockIdx.y * TPG;

    float c0[4][4] = {{0.f,0.f,0.f,0.f},{0.f,0.f,0.f,0.f},
                      {0.f,0.f,0.f,0.f},{0.f,0.f,0.f,0.f}};   // classes 0..7, ks mod 4
    ull acc8 = 0ull, acc9 = 0ull;                             // rows (r0,r1) packed

    const ull one = pk2(1.f, 1.f);
    const ull mone = pk2(-1.f, -1.f);

#pragma unroll 1
    for (int j = 0; j < TPG; j++) {
        int t = t0 + j;
        const float* sp = g_s + (size_t)t * DD * BB;
        float sA[DD], sB[DD];
#pragma unroll
        for (int d = 0; d < DD; d++) {
            sA[d] = __ldg(sp + (size_t)d * BB + r0);
            sB[d] = __ldg(sp + (size_t)d * BB + r1);
        }
        float aA = __ldg(g_attn + (size_t)t * BB + r0);
        float aB = __ldg(g_attn + (size_t)t * BB + r1);

        ull s0 = pk2(sA[0], sB[0]), s1 = pk2(sA[1], sB[1]), s2 = pk2(sA[2], sB[2]);
        ull s3 = pk2(sA[3], sB[3]), s4 = pk2(sA[4], sB[4]);
        ull s5 = pk2(sA[5], sB[5]), s6 = pk2(sA[6], sB[6]);
        ull aP = pk2(aA, aB);

        ull f0 = (tg & 1) ? fma2(s0, mone, one) : s0;
        ull f1 = (tg & 2) ? fma2(s1, mone, one) : s1;
        ull p = mul2(f0, f1);
        ull lo0 = mul2(p, s2);
        ull lo1 = mul2(p, fma2(s2, mone, one));

        ull h2_0 = mul2(aP, s3);
        ull h2_1 = mul2(aP, fma2(s3, mone, one));
        ull n4 = fma2(s4, mone, one);
        ull n5 = fma2(s5, mone, one);
        ull n6 = fma2(s6, mone, one);
        ull h4[4], fq[4];
        h4[0] = mul2(h2_0, s4); h4[1] = mul2(h2_1, s4);
        h4[2] = mul2(h2_0, n4); h4[3] = mul2(h2_1, n4);
        fq[0] = mul2(s5, s6); fq[1] = mul2(n5, s6);
        fq[2] = mul2(s5, n6); fq[3] = mul2(n5, n6);

        const float2* bp2 = (const float2*)g_lpf2 + (size_t)(t * 16) * 32 + lane;
        const float4* lpq = (const float4*)g_lp89q + (size_t)t * 64 + tg;
#pragma unroll
        for (int ks = 0; ks < 16; ks++) {
            float2 bf = __ldg(&bp2[ks * 32]);
            float4 q89 = __ldg(&lpq[ks * 4]);   // quad-uniform broadcast
            ull hk = mul2(h4[ks & 3], fq[ks >> 2]);
            ull a01 = mul2(hk, lo0);     // p at leaf ks*8+tg   (rows r0,r1)
            ull a23 = mul2(hk, lo1);     // p at leaf ks*8+tg+4 (rows r0,r1)
            float fa0, fa1, fa2, fa3;
            upk2(a01, fa0, fa1);
            upk2(a23, fa2, fa3);
            mma_tf32(c0[ks & 3], __float_as_uint(fa0), __float_as_uint(fa1),
                     __float_as_uint(fa2), __float_as_uint(fa3),
                     __float_as_uint(bf.x), __float_as_uint(bf.y));
            acc8 = fma2(a01, pk2(q89.x, q89.x), acc8);
            acc9 = fma2(a01, pk2(q89.y, q89.y), acc9);
            acc8 = fma2(a23, pk2(q89.z, q89.z), acc8);
            acc9 = fma2(a23, pk2(q89.w, q89.w), acc9);
        }
    }

    float* po0 = g_partial + ((size_t)blockIdx.y * BB + r0) * CC;
    float* po1 = g_partial + ((size_t)blockIdx.y * BB + r1) * CC;
    po0[tg * 2]     = (c0[0][0] + c0[1][0]) + (c0[2][0] + c0[3][0]);
    po0[tg * 2 + 1] = (c0[0][1] + c0[1][1]) + (c0[2][1] + c0[3][1]);
    po1[tg * 2]     = (c0[0][2] + c0[1][2]) + (c0[2][2] + c0[3][2]);
    po1[tg * 2 + 1] = (c0[0][3] + c0[1][3]) + (c0[2][3] + c0[3][3]);

    // reduce classes 8,9 across the 4 tg lanes of each quad
    float c8r0, c8r1, c9r0, c9r1;
    upk2(acc8, c8r0, c8r1);
    upk2(acc9, c9r0, c9r1);
#pragma unroll
    for (int o = 1; o <= 2; o <<= 1) {
        c8r0 += __shfl_xor_sync(0xffffffffu, c8r0, o);
        c8r1 += __shfl_xor_sync(0xffffffffu, c8r1, o);
        c9r0 += __shfl_xor_sync(0xffffffffu, c9r0, o);
        c9r1 += __shfl_xor_sync(0xffffffffu, c9r1, o);
    }
    if (tg == 0) {
        po0[8] = c8r0; po0[9] = c9r0;
        po1[8] = c8r1; po1[9] = c9r1;
    }
}

// ---------------------------------------------------------------------------
// Kernel 5: reduce NGR partials -> output
// ---------------------------------------------------------------------------
__global__ void k_reduce(float* __restrict__ out) {
    int i = blockIdx.x * 256 + threadIdx.x;
    if (i < BB * CC) {
        float v = 0.f;
#pragma unroll
        for (int g = 0; g < NGR; g++) v += g_partial[(size_t)g * BB * CC + i];
        out[i] = v;
    }
}

// ---------------------------------------------------------------------------
extern "C" void kernel_launch(void* const* d_in, const int* in_sizes, int n_in,
                              void* d_out, int out_size) {
    const float* x    = (const float*)d_in[0];
    const float* fm   = (const float*)d_in[1];
    const float* th   = (const float*)d_in[2];
    const float* leaf = (const float*)d_in[3];
    const float* W1   = (const float*)d_in[4];
    const float* b1   = (const float*)d_in[5];
    const float* W2   = (const float*)d_in[6];
    const float* b2   = (const float*)d_in[7];
    float* out = (float*)d_out;

    k_leafprep<<<64, 256>>>(leaf);
    k_zs_mma<<<dim3(32, 16), 256>>>(x, fm, th);
    k_attn<<<256, 256>>>(x, W1, b1, W2, b2);
    k_trees_mma<<<dim3(64, NGR), 256>>>();
    k_reduce<<<320, 256>>>(out);
}

// round 15
// speedup vs baseline: 1.1030x; 1.1030x over previous
#include <cuda_runtime.h>
#include <cstdint>
#include <math.h>

#define BB 8192
#define TT 128
#define DD 7
#define CC 10
#define LL 128
#define NCOL (TT*DD)   // 896
#define NGR 16         // tree groups
#define TPG (TT/NGR)   // 8 trees per group

// Scratch (device globals: allocation-free rule)
__device__ __align__(16) float g_s[(size_t)NCOL*BB];      // s[col][b]
__device__ __align__(16) float g_attn[(size_t)TT*BB];     // attn[t][b]
__device__ __align__(16) float g_lpf[TT*16*32*4];         // B frags [t][ks][lane]{b0n0,b1n0,b0n1,b1n1}
__device__ __align__(16) float g_partial[(size_t)NGR*BB*CC];

typedef unsigned long long ull;

// ---- packed fp32x2 helpers ------------------------------------------------
__device__ __forceinline__ ull pk2(float lo, float hi) {
    ull r;
    asm("mov.b64 %0, {%1, %2};" : "=l"(r) : "f"(lo), "f"(hi));
    return r;
}
__device__ __forceinline__ void upk2(ull v, float& lo, float& hi) {
    asm("mov.b64 {%0, %1}, %2;" : "=f"(lo), "=f"(hi) : "l"(v));
}
__device__ __forceinline__ ull fma2(ull a, ull b, ull c) {
    ull d;
    asm("fma.rn.f32x2 %0, %1, %2, %3;" : "=l"(d) : "l"(a), "l"(b), "l"(c));
    return d;
}
__device__ __forceinline__ ull mul2(ull a, ull b) {
    ull d;
    asm("mul.rn.f32x2 %0, %1, %2;" : "=l"(d) : "l"(a), "l"(b));
    return d;
}

// ---- tf32 / bf16 helpers ---------------------------------------------------
__device__ __forceinline__ float rna_tf32(float x) {
    float o;
    asm("cvt.rna.tf32.f32 %0, %1;" : "=f"(o) : "f"(x));
    return o;
}
__device__ __forceinline__ void mma_tf32(float* c, uint32_t a0, uint32_t a1,
                                         uint32_t a2, uint32_t a3,
                                         uint32_t b0, uint32_t b1) {
    asm volatile(
        "mma.sync.aligned.m16n8k8.row.col.f32.tf32.tf32.f32 "
        "{%0,%1,%2,%3}, {%4,%5,%6,%7}, {%8,%9}, {%0,%1,%2,%3};"
        : "+f"(c[0]), "+f"(c[1]), "+f"(c[2]), "+f"(c[3])
        : "r"(a0), "r"(a1), "r"(a2), "r"(a3), "r"(b0), "r"(b1));
}
__device__ __forceinline__ void mma_bf16(float* c, uint32_t a0, uint32_t a1,
                                         uint32_t a2, uint32_t a3,
                                         uint32_t b0, uint32_t b1) {
    asm volatile(
        "mma.sync.aligned.m16n8k16.row.col.f32.bf16.bf16.f32 "
        "{%0,%1,%2,%3}, {%4,%5,%6,%7}, {%8,%9}, {%0,%1,%2,%3};"
        : "+f"(c[0]), "+f"(c[1]), "+f"(c[2]), "+f"(c[3])
        : "r"(a0), "r"(a1), "r"(a2), "r"(a3), "r"(b0), "r"(b1));
}
// pack: lower 16 bits = bf16(even), upper = bf16(odd)
__device__ __forceinline__ uint32_t bf16x2_of(float even, float odd) {
    uint32_t d;
    asm("cvt.rn.bf16x2.f32 %0, %1, %2;" : "=r"(d) : "f"(odd), "f"(even));
    return d;
}

// ---------------------------------------------------------------------------
// Body: leaf softmax -> B fragments (tf32-RNA) in mma.sync layout.
// ---------------------------------------------------------------------------
__device__ void leafprep_body(const float* __restrict__ leaf, int row) {
    if (row >= TT * LL) return;
    int t = row >> 7, l = row & 127;
    const float* in = leaf + (size_t)row * CC;
    float m = in[0];
#pragma unroll
    for (int c = 1; c < CC; c++) m = fmaxf(m, in[c]);
    float e[CC]; float sum = 0.f;
#pragma unroll
    for (int c = 0; c < CC; c++) { e[c] = __expf(in[c] - m); sum += e[c]; }
    float inv = __fdividef(1.f, sum);
    float lp[CC];
#pragma unroll
    for (int c = 0; c < CC; c++) lp[c] = rna_tf32(e[c] * inv);

    int ks = l >> 3, kk = l & 7, tg = kk & 3, slot = kk >> 2;
    float* base = g_lpf + (size_t)((t * 16 + ks) * 32) * 4;
#pragma unroll
    for (int gid = 0; gid < 8; gid++) {
        float* o = base + (gid * 4 + tg) * 4;
        o[slot] = lp[gid];                               // n-tile 0: class gid
        o[2 + slot] = (gid < 2) ? lp[8 + gid] : 0.f;     // n-tile 1: class 8+gid
    }
}

// ---------------------------------------------------------------------------
// Body: z = x @ FM^T - th, s = 0.5*(z/(1+|z|)+1)  -> g_s[col][b]
// bf16 m16n8k16 hi/lo K-packed; one HMMA per (mf,nt,ks).
// ---------------------------------------------------------------------------
__device__ void zs_body(const float* __restrict__ x,
                        const float* __restrict__ fm,
                        const float* __restrict__ th,
                        int bx, int by) {
    int tid = threadIdx.x;
    int warp = tid >> 5, lane = tid & 31;
    int gid = lane >> 2, tg = lane & 3;
    int rbase = bx * 256 + warp * 32 + gid;   // rows rbase, +8, +16, +24
    int bn = by * 56;

    float c[2][7][4];
#pragma unroll
    for (int mf = 0; mf < 2; mf++)
#pragma unroll
        for (int nt = 0; nt < 7; nt++)
#pragma unroll
            for (int q = 0; q < 4; q++) c[mf][nt][q] = 0.f;

    const float* xr0 = x + (size_t)rbase * 128;
    const float* xr1 = x + (size_t)(rbase + 8) * 128;
    const float* xr2 = x + (size_t)(rbase + 16) * 128;
    const float* xr3 = x + (size_t)(rbase + 24) * 128;

#pragma unroll
    for (int ks = 0; ks < 16; ks++) {
        int kb = ks * 8 + 2 * tg;           // this thread's 2 adjacent features
        const float* xrs[4] = {xr0, xr1, xr2, xr3};
        uint32_t ah[4], al[4];
#pragma unroll
        for (int r = 0; r < 4; r++) {
            float2 xv = __ldg((const float2*)(xrs[r] + kb));
            uint32_t h = bf16x2_of(xv.x, xv.y);
            float fe = __uint_as_float(h << 16);
            float fo = __uint_as_float(h & 0xffff0000u);
            ah[r] = h;
            al[r] = bf16x2_of(xv.x - fe, xv.y - fo);   // exact residual, bf16-rounded
        }
#pragma unroll
        for (int nt = 0; nt < 7; nt++) {
            int col = bn + nt * 8 + gid;
            float2 fv = __ldg((const float2*)(fm + (size_t)col * 128 + kb));
            uint32_t bb = bf16x2_of(fv.x, fv.y);       // 0/1: exact
            mma_bf16(c[0][nt], ah[0], ah[1], al[0], al[1], bb, bb);
            mma_bf16(c[1][nt], ah[2], ah[3], al[2], al[3], bb, bb);
        }
    }

#pragma unroll
    for (int mf = 0; mf < 2; mf++) {
        int b0r = rbase + mf * 16;
#pragma unroll
        for (int nt = 0; nt < 7; nt++) {
            int col = bn + nt * 8 + tg * 2;
            float t0v = __ldg(th + col), t1v = __ldg(th + col + 1);
            float z0 = c[mf][nt][0] - t0v;
            float z1 = c[mf][nt][1] - t1v;
            float z2 = c[mf][nt][2] - t0v;
            float z3 = c[mf][nt][3] - t1v;
            g_s[(size_t)col * BB + b0r]           = 0.5f * (__fdividef(z0, 1.0f + fabsf(z0)) + 1.0f);
            g_s[(size_t)(col + 1) * BB + b0r]     = 0.5f * (__fdividef(z1, 1.0f + fabsf(z1)) + 1.0f);
            g_s[(size_t)col * BB + b0r + 8]       = 0.5f * (__fdividef(z2, 1.0f + fabsf(z2)) + 1.0f);
            g_s[(size_t)(col + 1) * BB + b0r + 8] = 0.5f * (__fdividef(z3, 1.0f + fabsf(z3)) + 1.0f);
        }
    }
}

// ---------------------------------------------------------------------------
// Body: attn = softmax(relu(x@W1+b1)@W2+b2)  -> g_attn[t][b]
// sh: 10368 floats (xst 4096 | hst 2048 | stage 4224)
// ---------------------------------------------------------------------------
__device__ void attn_body(const float* __restrict__ x,
                          const float* __restrict__ W1,
                          const float* __restrict__ b1,
                          const float* __restrict__ W2,
                          const float* __restrict__ b2,
                          float* sh, int ab) {
    float* xst = sh;            // 128*32
    float* hst = sh + 4096;     // 64*32
    float* stage = sh + 6144;   // 128*33
    int tid = threadIdx.x;
    int b0 = ab * 32;
#pragma unroll
    for (int j = 0; j < 4; j++) {
        int idx = tid + 256 * j;
        int bl = idx & 31;
        int kq = (idx >> 5) * 4;
        float4 v = *(const float4*)(x + (size_t)(b0 + bl) * 128 + kq);
        xst[(kq + 0) * 32 + bl] = v.x; xst[(kq + 1) * 32 + bl] = v.y;
        xst[(kq + 2) * 32 + bl] = v.z; xst[(kq + 3) * 32 + bl] = v.w;
    }
    int bl = tid & 31;
    int grp = tid >> 5;
    ull hacc2[4] = {0ull, 0ull, 0ull, 0ull};
    for (int kc = 0; kc < 128; kc += 64) {
        __syncthreads();
#pragma unroll
        for (int j = 0; j < 4; j++) {
            int idx = tid + 256 * j;
            ((float4*)stage)[idx] = *((const float4*)(W1 + (size_t)kc * 64) + idx);
        }
        __syncthreads();
#pragma unroll 8
        for (int k = 0; k < 64; k++) {
            float xv = xst[(kc + k) * 32 + bl];
            ull xp = pk2(xv, xv);
            ulonglong2 w0 = *(const ulonglong2*)&stage[k * 64 + grp * 8];
            ulonglong2 w1 = *(const ulonglong2*)&stage[k * 64 + grp * 8 + 4];
            hacc2[0] = fma2(xp, w0.x, hacc2[0]);
            hacc2[1] = fma2(xp, w0.y, hacc2[1]);
            hacc2[2] = fma2(xp, w1.x, hacc2[2]);
            hacc2[3] = fma2(xp, w1.y, hacc2[3]);
        }
    }
#pragma unroll
    for (int jj = 0; jj < 4; jj++) {
        float h0, h1;
        upk2(hacc2[jj], h0, h1);
        h0 += __ldg(b1 + grp * 8 + 2 * jj);
        h1 += __ldg(b1 + grp * 8 + 2 * jj + 1);
        hst[(grp * 8 + 2 * jj) * 32 + bl] = fmaxf(h0, 0.f);
        hst[(grp * 8 + 2 * jj + 1) * 32 + bl] = fmaxf(h1, 0.f);
    }
    ull lacc2[8];
#pragma unroll
    for (int j = 0; j < 8; j++) lacc2[j] = 0ull;
    for (int kc = 0; kc < 64; kc += 32) {
        __syncthreads();
#pragma unroll
        for (int j = 0; j < 4; j++) {
            int idx = tid + 256 * j;
            ((float4*)stage)[idx] = *((const float4*)(W2 + (size_t)kc * 128) + idx);
        }
        __syncthreads();
#pragma unroll 4
        for (int k = 0; k < 32; k++) {
            float hv = hst[(kc + k) * 32 + bl];
            ull hp = pk2(hv, hv);
            const ulonglong2* wr = (const ulonglong2*)&stage[k * 128 + grp * 16];
            ulonglong2 q0 = wr[0], q1 = wr[1], q2 = wr[2], q3 = wr[3];
            lacc2[0] = fma2(hp, q0.x, lacc2[0]); lacc2[1] = fma2(hp, q0.y, lacc2[1]);
            lacc2[2] = fma2(hp, q1.x, lacc2[2]); lacc2[3] = fma2(hp, q1.y, lacc2[3]);
            lacc2[4] = fma2(hp, q2.x, lacc2[4]); lacc2[5] = fma2(hp, q2.y, lacc2[5]);
            lacc2[6] = fma2(hp, q3.x, lacc2[6]); lacc2[7] = fma2(hp, q3.y, lacc2[7]);
        }
    }
    __syncthreads();
#pragma unroll
    for (int jj = 0; jj < 8; jj++) {
        float l0, l1;
        upk2(lacc2[jj], l0, l1);
        stage[(grp * 16 + 2 * jj) * 33 + bl] = l0 + __ldg(b2 + grp * 16 + 2 * jj);
        stage[(grp * 16 + 2 * jj + 1) * 33 + bl] = l1 + __ldg(b2 + grp * 16 + 2 * jj + 1);
    }
    __syncthreads();
    int lane = bl;
    for (int r4 = 0; r4 < 4; r4++) {
        int r = grp * 4 + r4;
        float v0 = stage[(lane +  0) * 33 + r];
        float v1 = stage[(lane + 32) * 33 + r];
        float v2 = stage[(lane + 64) * 33 + r];
        float v3 = stage[(lane + 96) * 33 + r];
        float m = fmaxf(fmaxf(v0, v1), fmaxf(v2, v3));
#pragma unroll
        for (int o = 16; o > 0; o >>= 1) m = fmaxf(m, __shfl_xor_sync(0xffffffffu, m, o));
        float e0 = __expf(v0 - m), e1 = __expf(v1 - m), e2 = __expf(v2 - m), e3 = __expf(v3 - m);
        float s = e0 + e1 + e2 + e3;
#pragma unroll
        for (int o = 16; o > 0; o >>= 1) s += __shfl_xor_sync(0xffffffffu, s, o);
        float inv = __fdividef(1.f, s);
        int gb = b0 + r;
        g_attn[(size_t)(lane +  0) * BB + gb] = e0 * inv;
        g_attn[(size_t)(lane + 32) * BB + gb] = e1 * inv;
        g_attn[(size_t)(lane + 64) * BB + gb] = e2 * inv;
        g_attn[(size_t)(lane + 96) * BB + gb] = e3 * inv;
    }
}

// ---------------------------------------------------------------------------
// Kernel A (fused front): blocks [0,512): zs | [512,768): attn | [768,832): leafprep
// ---------------------------------------------------------------------------
__global__ __launch_bounds__(256) void k_front(const float* __restrict__ x,
                                               const float* __restrict__ fm,
                                               const float* __restrict__ th,
                                               const float* __restrict__ leaf,
                                               const float* __restrict__ W1,
                                               const float* __restrict__ b1,
                                               const float* __restrict__ W2,
                                               const float* __restrict__ b2) {
    __shared__ __align__(16) float sh[10368];   // used by attn branch only
    int bid = blockIdx.x;
    if (bid < 512) {
        zs_body(x, fm, th, bid & 31, bid >> 5);
    } else if (bid < 768) {
        attn_body(x, W1, b1, W2, b2, sh, bid - 512);
    } else {
        leafprep_body(leaf, (bid - 768) * 256 + threadIdx.x);
    }
}

// ---------------------------------------------------------------------------
// Kernel B: tree eval via mma.sync tf32 (round-7 version: best known).
// ---------------------------------------------------------------------------
__global__ __launch_bounds__(256, 3) void k_trees_mma() {
    int tid = threadIdx.x;
    int warp = tid >> 5, lane = tid & 31;
    int gid = lane >> 2, tg = lane & 3;
    int r0 = blockIdx.x * 128 + warp * 16 + gid;
    int r1 = r0 + 8;
    int t0 = blockIdx.y * TPG;

    float c0[4][4] = {{0.f,0.f,0.f,0.f},{0.f,0.f,0.f,0.f},
                      {0.f,0.f,0.f,0.f},{0.f,0.f,0.f,0.f}};   // classes 0..7, ks mod 4
    float c1[2][4] = {{0.f,0.f,0.f,0.f},{0.f,0.f,0.f,0.f}};   // classes 8,9, ks parity

    const ull one = pk2(1.f, 1.f);
    const ull mone = pk2(-1.f, -1.f);

#pragma unroll 1
    for (int j = 0; j < TPG; j++) {
        int t = t0 + j;
        const float* sp = g_s + (size_t)t * DD * BB;
        float sA[DD], sB[DD];
#pragma unroll
        for (int d = 0; d < DD; d++) {
            sA[d] = __ldg(sp + (size_t)d * BB + r0);
            sB[d] = __ldg(sp + (size_t)d * BB + r1);
        }
        float aA = __ldg(g_attn + (size_t)t * BB + r0);
        float aB = __ldg(g_attn + (size_t)t * BB + r1);

        ull s0 = pk2(sA[0], sB[0]), s1 = pk2(sA[1], sB[1]), s2 = pk2(sA[2], sB[2]);
        ull s3 = pk2(sA[3], sB[3]), s4 = pk2(sA[4], sB[4]);
        ull s5 = pk2(sA[5], sB[5]), s6 = pk2(sA[6], sB[6]);
        ull aP = pk2(aA, aB);

        ull f0 = (tg & 1) ? fma2(s0, mone, one) : s0;
        ull f1 = (tg & 2) ? fma2(s1, mone, one) : s1;
        ull p = mul2(f0, f1);
        ull lo0 = mul2(p, s2);
        ull lo1 = mul2(p, fma2(s2, mone, one));

        ull h2_0 = mul2(aP, s3);
        ull h2_1 = mul2(aP, fma2(s3, mone, one));
        ull n4 = fma2(s4, mone, one);
        ull n5 = fma2(s5, mone, one);
        ull n6 = fma2(s6, mone, one);
        ull h4[4], fq[4];
        h4[0] = mul2(h2_0, s4); h4[1] = mul2(h2_1, s4);
        h4[2] = mul2(h2_0, n4); h4[3] = mul2(h2_1, n4);
        fq[0] = mul2(s5, s6); fq[1] = mul2(n5, s6);
        fq[2] = mul2(s5, n6); fq[3] = mul2(n5, n6);

        const float4* bp = (const float4*)g_lpf + (size_t)(t * 16) * 32 + lane;
#pragma unroll
        for (int ks = 0; ks < 16; ks++) {
            float4 bf = __ldg(&bp[ks * 32]);
            ull hk = mul2(h4[ks & 3], fq[ks >> 2]);
            ull a01 = mul2(hk, lo0);
            ull a23 = mul2(hk, lo1);
            float fa0, fa1, fa2, fa3;
            upk2(a01, fa0, fa1);
            upk2(a23, fa2, fa3);
            mma_tf32(c0[ks & 3], __float_as_uint(fa0), __float_as_uint(fa1),
                     __float_as_uint(fa2), __float_as_uint(fa3),
                     __float_as_uint(bf.x), __float_as_uint(bf.y));
            mma_tf32(c1[ks & 1], __float_as_uint(fa0), __float_as_uint(fa1),
                     __float_as_uint(fa2), __float_as_uint(fa3),
                     __float_as_uint(bf.z), __float_as_uint(bf.w));
        }
    }

    float* po0 = g_partial + ((size_t)blockIdx.y * BB + r0) * CC;
    float* po1 = g_partial + ((size_t)blockIdx.y * BB + r1) * CC;
    po0[tg * 2]     = (c0[0][0] + c0[1][0]) + (c0[2][0] + c0[3][0]);
    po0[tg * 2 + 1] = (c0[0][1] + c0[1][1]) + (c0[2][1] + c0[3][1]);
    po1[tg * 2]     = (c0[0][2] + c0[1][2]) + (c0[2][2] + c0[3][2]);
    po1[tg * 2 + 1] = (c0[0][3] + c0[1][3]) + (c0[2][3] + c0[3][3]);
    if (tg == 0) {
        po0[8] = c1[0][0] + c1[1][0]; po0[9] = c1[0][1] + c1[1][1];
        po1[8] = c1[0][2] + c1[1][2]; po1[9] = c1[0][3] + c1[1][3];
    }
}

// ---------------------------------------------------------------------------
// Kernel C: reduce NGR partials -> output
// ---------------------------------------------------------------------------
__global__ void k_reduce(float* __restrict__ out) {
    int i = blockIdx.x * 256 + threadIdx.x;
    if (i < BB * CC) {
        float v = 0.f;
#pragma unroll
        for (int g = 0; g < NGR; g++) v += g_partial[(size_t)g * BB * CC + i];
        out[i] = v;
    }
}

// ---------------------------------------------------------------------------
extern "C" void kernel_launch(void* const* d_in, const int* in_sizes, int n_in,
                              void* d_out, int out_size) {
    const float* x    = (const float*)d_in[0];
    const float* fm   = (const float*)d_in[1];
    const float* th   = (const float*)d_in[2];
    const float* leaf = (const float*)d_in[3];
    const float* W1   = (const float*)d_in[4];
    const float* b1   = (const float*)d_in[5];
    const float* W2   = (const float*)d_in[6];
    const float* b2   = (const float*)d_in[7];
    float* out = (float*)d_out;

    k_front<<<832, 256>>>(x, fm, th, leaf, W1, b1, W2, b2);
    k_trees_mma<<<dim3(64, NGR), 256>>>();
    k_reduce<<<320, 256>>>(out);
}